// round 7
// baseline (speedup 1.0000x reference)
#include <cuda_runtime.h>
#include <cuda_fp16.h>
#include <cstdint>

#define BATCH 8
#define CCH   64
#define DQ    8
#define NPIX  4096
#define TM    128
#define TN    128
#define NT    (NPIX / TN)
#define L2E   1.4426950408889634f

__device__ __half g_q16[BATCH * NPIX * DQ];                 // pre-scaled by log2(e)
__device__ __half g_k16[BATCH * NPIX * DQ];
__device__ float  g_qn[BATCH * NPIX];
__device__ __half g_v16[(size_t)BATCH * CCH * NPIX];        // [b][c][n]
__device__ float  g_kmax_part[BATCH * 32];

__device__ __forceinline__ uint32_t s2u(const void* p) {
    uint32_t a;
    asm("{ .reg .u64 t; cvta.to.shared.u64 t, %1; cvt.u32.u64 %0, t; }" : "=r"(a) : "l"(p));
    return a;
}
#define CP16(dst, src) asm volatile("cp.async.cg.shared.global [%0], [%1], 16;" :: "r"(dst), "l"(src) : "memory")
#define CPCOMMIT()     asm volatile("cp.async.commit_group;" ::: "memory")
#define CPWAIT1()      asm volatile("cp.async.wait_group 1;" ::: "memory")
#define CPWAIT0()      asm volatile("cp.async.wait_group 0;" ::: "memory")

// ---------------------------------------------------------------------------
// QKV projection (128 thr, grid (32, B)).
// ---------------------------------------------------------------------------
__global__ __launch_bounds__(128) void qkv_kernel(
    const float* __restrict__ x,
    const float* __restrict__ wq, const float* __restrict__ bq,
    const float* __restrict__ wk, const float* __restrict__ bk,
    const float* __restrict__ wv, const float* __restrict__ bv)
{
    __shared__ float swq[DQ * CCH], swk[DQ * CCH], swv[CCH * CCH];
    __shared__ float sbq[DQ], sbk[DQ], sbv[CCH];
    __shared__ float swmax[4];

    const int tid = threadIdx.x;
    const int b = blockIdx.y;

    for (int i = tid; i < DQ * CCH; i += 128) { swq[i] = wq[i]; swk[i] = wk[i]; }
    for (int i = tid; i < CCH * CCH; i += 128) swv[i] = wv[i];
    if (tid < DQ) { sbq[tid] = bq[tid]; sbk[tid] = bk[tid]; }
    if (tid < CCH) sbv[tid] = bv[tid];
    __syncthreads();

    const int n = blockIdx.x * 128 + tid;

    float xv[CCH];
    const float* xb = x + ((size_t)b * CCH) * NPIX + n;
    #pragma unroll
    for (int c = 0; c < CCH; c++) xv[c] = xb[(size_t)c * NPIX];

    float qv[DQ], kv[DQ];
    #pragma unroll
    for (int d = 0; d < DQ; d++) {
        float aq = sbq[d], ak = sbk[d];
        #pragma unroll
        for (int c = 0; c < CCH; c++) {
            aq = fmaf(swq[d * CCH + c], xv[c], aq);
            ak = fmaf(swk[d * CCH + c], xv[c], ak);
        }
        qv[d] = aq; kv[d] = ak;
    }
    {
        __half2* qo = (__half2*)&g_q16[((size_t)b * NPIX + n) * DQ];
        __half2* ko = (__half2*)&g_k16[((size_t)b * NPIX + n) * DQ];
        #pragma unroll
        for (int d = 0; d < 4; d++) {
            qo[d] = __floats2half2_rn(qv[2*d] * L2E, qv[2*d+1] * L2E);
            ko[d] = __floats2half2_rn(kv[2*d], kv[2*d+1]);
        }
    }
    {
        float nq2 = 0.f, nk2 = 0.f;
        #pragma unroll
        for (int d = 0; d < DQ; d++) {
            nq2 = fmaf(qv[d], qv[d], nq2);
            nk2 = fmaf(kv[d], kv[d], nk2);
        }
        g_qn[b * NPIX + n] = sqrtf(nq2);
        float nk = sqrtf(nk2);
        #pragma unroll
        for (int off = 16; off > 0; off >>= 1)
            nk = fmaxf(nk, __shfl_xor_sync(0xFFFFFFFFu, nk, off));
        if ((tid & 31) == 0) swmax[tid >> 5] = nk;
        __syncthreads();
        if (tid == 0)
            g_kmax_part[b * 32 + blockIdx.x] =
                fmaxf(fmaxf(swmax[0], swmax[1]), fmaxf(swmax[2], swmax[3]));
    }
    #pragma unroll 4
    for (int o = 0; o < CCH; o += 4) {
        float a0 = sbv[o+0], a1 = sbv[o+1], a2 = sbv[o+2], a3 = sbv[o+3];
        #pragma unroll
        for (int c = 0; c < CCH; c++) {
            float xc = xv[c];
            a0 = fmaf(swv[(o+0)*CCH + c], xc, a0);
            a1 = fmaf(swv[(o+1)*CCH + c], xc, a1);
            a2 = fmaf(swv[(o+2)*CCH + c], xc, a2);
            a3 = fmaf(swv[(o+3)*CCH + c], xc, a3);
        }
        g_v16[((size_t)(b*CCH + o+0))*NPIX + n] = __float2half_rn(a0);
        g_v16[((size_t)(b*CCH + o+1))*NPIX + n] = __float2half_rn(a1);
        g_v16[((size_t)(b*CCH + o+2))*NPIX + n] = __float2half_rn(a2);
        g_v16[((size_t)(b*CCH + o+3))*NPIX + n] = __float2half_rn(a3);
    }
}

// ---------------------------------------------------------------------------
// Flash attention, 256 threads (8 warps): warp = (mw, h), mw = m-group of 32
// rows (mt=2 x m16), h = channel half (4 of 8 jc groups). S/exp duplicated
// across h; V smem traffic same as 4-warp version; 2x resident warps.
// Grid (32, 8).
// ---------------------------------------------------------------------------
#define STAGE(t, buf) do { \
    if (tid < TN) { \
        const __half* _ks = g_k16 + ((size_t)b * NPIX + (t) * TN + tid) * DQ; \
        CP16(s2u(&sK[buf][tid][0]), _ks); \
    } \
    _Pragma("unroll") \
    for (int _i = 0; _i < 4; _i++) { \
        int _l = _i * 256 + tid, _row = _l >> 4, _seg = _l & 15; \
        const __half* _vs = g_v16 + ((size_t)(b * CCH + _row)) * NPIX + (t) * TN + _seg * 8; \
        CP16(s2u(&sV[buf][_row][_seg * 8]), _vs); \
    } \
} while (0)

__global__ __launch_bounds__(256) void attn_kernel(
    const float* __restrict__ x,
    const float* __restrict__ gamma,
    float* __restrict__ out)
{
    __shared__ __align__(16) __half sK[2][TN][24];
    __shared__ __align__(16) __half sV[2][CCH][136];

    const int tid  = threadIdx.x;
    const int w    = tid >> 5;
    const int lane = tid & 31;
    const int g    = lane >> 2;
    const int c    = lane & 3;
    const int mw   = w & 3;          // m-group (32 rows)
    const int h    = w >> 2;         // channel half
    const int b    = blockIdx.y;
    const int m0   = blockIdx.x * TM + mw * 32;

    float kmax = g_kmax_part[b * 32];
    #pragma unroll
    for (int i = 1; i < 32; i++) kmax = fmaxf(kmax, g_kmax_part[b * 32 + i]);

    uint32_t qa0[2], qa1[2];
    float nsh[4];
    #pragma unroll
    for (int mt = 0; mt < 2; mt++) {
        const int rA = m0 + mt * 16 + g, rB = rA + 8;
        qa0[mt] = *(const uint32_t*)&g_q16[((size_t)b * NPIX + rA) * DQ + 2 * c];
        qa1[mt] = *(const uint32_t*)&g_q16[((size_t)b * NPIX + rB) * DQ + 2 * c];
        nsh[2*mt]   = -g_qn[b * NPIX + rA] * kmax * L2E;
        nsh[2*mt+1] = -g_qn[b * NPIX + rB] * kmax * L2E;
    }

    float acc[2][4][4];
    #pragma unroll
    for (int mt = 0; mt < 2; mt++)
        #pragma unroll
        for (int jl = 0; jl < 4; jl++)
            #pragma unroll
            for (int r = 0; r < 4; r++) acc[mt][jl][r] = 0.f;
    float ls[4] = {0.f, 0.f, 0.f, 0.f};

    STAGE(0, 0); CPCOMMIT();

    #pragma unroll 1
    for (int t = 0; t < NT; t++) {
        if (t + 1 < NT) { STAGE(t + 1, (t + 1) & 1); CPCOMMIT(); CPWAIT1(); }
        else            { CPWAIT0(); }
        __syncthreads();
        const __half (*K)[24]  = sK[t & 1];
        const __half (*V)[136] = sV[t & 1];

        #pragma unroll
        for (int kc = 0; kc < 8; kc++) {
            const uint32_t kb0 = *(const uint32_t*)&K[kc * 16 + g][2 * c];
            const uint32_t kb1 = *(const uint32_t*)&K[kc * 16 + 8 + g][2 * c];
            uint32_t pf[2][4];
            #pragma unroll
            for (int mt = 0; mt < 2; mt++) {
                float s0, s1, s2, s3;
                asm volatile(
                    "mma.sync.aligned.m16n8k8.row.col.f32.f16.f16.f32 "
                    "{%0,%1,%2,%3},{%4,%5},{%6},{%7,%8,%9,%10};"
                    : "=f"(s0), "=f"(s1), "=f"(s2), "=f"(s3)
                    : "r"(qa0[mt]), "r"(qa1[mt]), "r"(kb0),
                      "f"(nsh[2*mt]), "f"(nsh[2*mt]), "f"(nsh[2*mt+1]), "f"(nsh[2*mt+1]));
                uint32_t u0, u1;
                asm("cvt.rn.f16x2.f32 %0, %1, %2;" : "=r"(u0) : "f"(s1), "f"(s0));
                asm("cvt.rn.f16x2.f32 %0, %1, %2;" : "=r"(u1) : "f"(s3), "f"(s2));
                asm("ex2.approx.f16x2 %0, %1;" : "=r"(pf[mt][0]) : "r"(u0));
                asm("ex2.approx.f16x2 %0, %1;" : "=r"(pf[mt][1]) : "r"(u1));
                asm volatile(
                    "mma.sync.aligned.m16n8k8.row.col.f32.f16.f16.f32 "
                    "{%0,%1,%2,%3},{%4,%5},{%6},{%7,%8,%9,%10};"
                    : "=f"(s0), "=f"(s1), "=f"(s2), "=f"(s3)
                    : "r"(qa0[mt]), "r"(qa1[mt]), "r"(kb1),
                      "f"(nsh[2*mt]), "f"(nsh[2*mt]), "f"(nsh[2*mt+1]), "f"(nsh[2*mt+1]));
                asm("cvt.rn.f16x2.f32 %0, %1, %2;" : "=r"(u0) : "f"(s1), "f"(s0));
                asm("cvt.rn.f16x2.f32 %0, %1, %2;" : "=r"(u1) : "f"(s3), "f"(s2));
                asm("ex2.approx.f16x2 %0, %1;" : "=r"(pf[mt][2]) : "r"(u0));
                asm("ex2.approx.f16x2 %0, %1;" : "=r"(pf[mt][3]) : "r"(u1));
            }
            // lsum on alu/fma pipes (only h==0's values are used, but computing
            // in both halves is cheaper than a cross-warp reduce)
            #pragma unroll
            for (int mt = 0; mt < 2; mt++) {
                __half2 hA = __hadd2(*(__half2*)&pf[mt][0], *(__half2*)&pf[mt][2]);
                __half2 hB = __hadd2(*(__half2*)&pf[mt][1], *(__half2*)&pf[mt][3]);
                float2 fA = __half22float2(hA);
                float2 fB = __half22float2(hB);
                ls[2*mt]   += fA.x + fA.y;
                ls[2*mt+1] += fB.x + fB.y;
            }
            // PV: this warp's 4 channel groups
            #pragma unroll
            for (int jl = 0; jl < 4; jl++) {
                const int jc = h * 4 + jl;
                const uint32_t b0 = *(const uint32_t*)&V[jc * 8 + g][kc * 16 + 2 * c];
                const uint32_t b1 = *(const uint32_t*)&V[jc * 8 + g][kc * 16 + 2 * c + 8];
                #pragma unroll
                for (int mt = 0; mt < 2; mt++) {
                    asm volatile(
                        "mma.sync.aligned.m16n8k16.row.col.f32.f16.f16.f32 "
                        "{%0,%1,%2,%3},{%4,%5,%6,%7},{%8,%9},{%0,%1,%2,%3};"
                        : "+f"(acc[mt][jl][0]), "+f"(acc[mt][jl][1]),
                          "+f"(acc[mt][jl][2]), "+f"(acc[mt][jl][3])
                        : "r"(pf[mt][0]), "r"(pf[mt][1]), "r"(pf[mt][2]), "r"(pf[mt][3]),
                          "r"(b0), "r"(b1));
                }
            }
        }
        __syncthreads();
    }

    // quad-reduce lsum
    #pragma unroll
    for (int i = 0; i < 4; i++) {
        ls[i] += __shfl_xor_sync(0xFFFFFFFFu, ls[i], 1);
        ls[i] += __shfl_xor_sync(0xFFFFFFFFu, ls[i], 2);
    }

    const float gm = gamma[0];
    const float* xb = x   + (size_t)b * CCH * NPIX;
    float*       ob = out + (size_t)b * CCH * NPIX;
    #pragma unroll
    for (int mt = 0; mt < 2; mt++) {
        const float iA = 1.f / ls[2*mt], iB = 1.f / ls[2*mt+1];
        const int rA = m0 + mt * 16 + g, rB = rA + 8;
        #pragma unroll
        for (int jl = 0; jl < 4; jl++) {
            const int ch0 = (h * 4 + jl) * 8 + 2 * c, ch1 = ch0 + 1;
            ob[(size_t)ch0 * NPIX + rA] = fmaf(gm, acc[mt][jl][0] * iA, xb[(size_t)ch0 * NPIX + rA]);
            ob[(size_t)ch1 * NPIX + rA] = fmaf(gm, acc[mt][jl][1] * iA, xb[(size_t)ch1 * NPIX + rA]);
            ob[(size_t)ch0 * NPIX + rB] = fmaf(gm, acc[mt][jl][2] * iB, xb[(size_t)ch0 * NPIX + rB]);
            ob[(size_t)ch1 * NPIX + rB] = fmaf(gm, acc[mt][jl][3] * iB, xb[(size_t)ch1 * NPIX + rB]);
        }
    }
}

// ---------------------------------------------------------------------------
extern "C" void kernel_launch(void* const* d_in, const int* in_sizes, int n_in,
                              void* d_out, int out_size)
{
    const float* x     = (const float*)d_in[0];
    const float* wq    = (const float*)d_in[1];
    const float* bq    = (const float*)d_in[2];
    const float* wk    = (const float*)d_in[3];
    const float* bk    = (const float*)d_in[4];
    const float* wv    = (const float*)d_in[5];
    const float* bv    = (const float*)d_in[6];
    const float* gamma = (const float*)d_in[7];
    float* out = (float*)d_out;

    dim3 g1(NPIX / 128, BATCH);
    qkv_kernel<<<g1, 128>>>(x, wq, bq, wk, bk, wv, bv);
    dim3 g2(NPIX / TM, BATCH);
    attn_kernel<<<g2, 256>>>(x, gamma, out);
}

// round 8
// speedup vs baseline: 1.0268x; 1.0268x over previous
#include <cuda_runtime.h>
#include <cuda_fp16.h>
#include <cstdint>

#define BATCH 8
#define CCH   64
#define DQ    8
#define NPIX  4096
#define TM    128
#define TN    128
#define NT    (NPIX / TN)
#define L2E   1.4426950408889634f

__device__ __half   g_q16[BATCH * NPIX * DQ];               // pre-scaled by log2(e)
__device__ __half   g_k16[BATCH * NPIX * DQ];
__device__ float    g_qn[BATCH * NPIX];
__device__ uint8_t  g_v8[(size_t)BATCH * CCH * NPIX];       // e4m3 [b][c][n]
__device__ float    g_kmax_part[BATCH * 32];

__device__ __forceinline__ uint32_t s2u(const void* p) {
    uint32_t a;
    asm("{ .reg .u64 t; cvta.to.shared.u64 t, %1; cvt.u32.u64 %0, t; }" : "=r"(a) : "l"(p));
    return a;
}
#define CP16(dst, src) asm volatile("cp.async.cg.shared.global [%0], [%1], 16;" :: "r"(dst), "l"(src) : "memory")
#define CPCOMMIT()     asm volatile("cp.async.commit_group;" ::: "memory")
#define CPWAIT1()      asm volatile("cp.async.wait_group 1;" ::: "memory")
#define CPWAIT0()      asm volatile("cp.async.wait_group 0;" ::: "memory")

// ---------------------------------------------------------------------------
// QKV projection (128 thr, grid (32, B)). q,k f16; v e4m3.
// ---------------------------------------------------------------------------
__global__ __launch_bounds__(128) void qkv_kernel(
    const float* __restrict__ x,
    const float* __restrict__ wq, const float* __restrict__ bq,
    const float* __restrict__ wk, const float* __restrict__ bk,
    const float* __restrict__ wv, const float* __restrict__ bv)
{
    __shared__ float swq[DQ * CCH], swk[DQ * CCH], swv[CCH * CCH];
    __shared__ float sbq[DQ], sbk[DQ], sbv[CCH];
    __shared__ float swmax[4];

    const int tid = threadIdx.x;
    const int b = blockIdx.y;

    for (int i = tid; i < DQ * CCH; i += 128) { swq[i] = wq[i]; swk[i] = wk[i]; }
    for (int i = tid; i < CCH * CCH; i += 128) swv[i] = wv[i];
    if (tid < DQ) { sbq[tid] = bq[tid]; sbk[tid] = bk[tid]; }
    if (tid < CCH) sbv[tid] = bv[tid];
    __syncthreads();

    const int n = blockIdx.x * 128 + tid;

    float xv[CCH];
    const float* xb = x + ((size_t)b * CCH) * NPIX + n;
    #pragma unroll
    for (int c = 0; c < CCH; c++) xv[c] = xb[(size_t)c * NPIX];

    float qv[DQ], kv[DQ];
    #pragma unroll
    for (int d = 0; d < DQ; d++) {
        float aq = sbq[d], ak = sbk[d];
        #pragma unroll
        for (int c = 0; c < CCH; c++) {
            aq = fmaf(swq[d * CCH + c], xv[c], aq);
            ak = fmaf(swk[d * CCH + c], xv[c], ak);
        }
        qv[d] = aq; kv[d] = ak;
    }
    {
        __half2* qo = (__half2*)&g_q16[((size_t)b * NPIX + n) * DQ];
        __half2* ko = (__half2*)&g_k16[((size_t)b * NPIX + n) * DQ];
        #pragma unroll
        for (int d = 0; d < 4; d++) {
            qo[d] = __floats2half2_rn(qv[2*d] * L2E, qv[2*d+1] * L2E);
            ko[d] = __floats2half2_rn(kv[2*d], kv[2*d+1]);
        }
    }
    {
        float nq2 = 0.f, nk2 = 0.f;
        #pragma unroll
        for (int d = 0; d < DQ; d++) {
            nq2 = fmaf(qv[d], qv[d], nq2);
            nk2 = fmaf(kv[d], kv[d], nk2);
        }
        g_qn[b * NPIX + n] = sqrtf(nq2);
        float nk = sqrtf(nk2);
        #pragma unroll
        for (int off = 16; off > 0; off >>= 1)
            nk = fmaxf(nk, __shfl_xor_sync(0xFFFFFFFFu, nk, off));
        if ((tid & 31) == 0) swmax[tid >> 5] = nk;
        __syncthreads();
        if (tid == 0)
            g_kmax_part[b * 32 + blockIdx.x] =
                fmaxf(fmaxf(swmax[0], swmax[1]), fmaxf(swmax[2], swmax[3]));
    }
    #pragma unroll 4
    for (int o = 0; o < CCH; o += 2) {
        float a0 = sbv[o+0], a1 = sbv[o+1];
        #pragma unroll
        for (int c = 0; c < CCH; c++) {
            float xc = xv[c];
            a0 = fmaf(swv[(o+0)*CCH + c], xc, a0);
            a1 = fmaf(swv[(o+1)*CCH + c], xc, a1);
        }
        uint16_t pk;   // {hi = a1, lo = a0}
        asm("cvt.rn.satfinite.e4m3x2.f32 %0, %1, %2;" : "=h"(pk) : "f"(a1), "f"(a0));
        g_v8[((size_t)(b*CCH + o+0))*NPIX + n] = (uint8_t)(pk & 0xFF);
        g_v8[((size_t)(b*CCH + o+1))*NPIX + n] = (uint8_t)(pk >> 8);
    }
}

// ---------------------------------------------------------------------------
// Flash attention: S = f16 HMMA k8, P -> e4m3 in-register repack,
// PV = FP8 HMMA m16n8k32 (half the tensor cycles of f16 k16).
// Grid (32, 8), 128 threads (4 warps); warp owns 32 m-rows, all 64 ch.
// ---------------------------------------------------------------------------
#define STAGE(t, buf) do { \
    const __half* _ks = g_k16 + ((size_t)b * NPIX + (t) * TN + tid) * DQ; \
    CP16(s2u(&sK[buf][tid][0]), _ks); \
    _Pragma("unroll") \
    for (int _i = 0; _i < 4; _i++) { \
        int _l = _i * 128 + tid, _row = _l >> 3, _seg = _l & 7; \
        const uint8_t* _vs = g_v8 + ((size_t)(b * CCH + _row)) * NPIX + (t) * TN + _seg * 16; \
        CP16(s2u(&sV8[buf][_row][_seg * 16]), _vs); \
    } \
} while (0)

__global__ __launch_bounds__(128) void attn_kernel(
    const float* __restrict__ x,
    const float* __restrict__ gamma,
    float* __restrict__ out)
{
    __shared__ __align__(16) __half   sK[2][TN][24];     // 48B stride, conflict-free
    __shared__ __align__(16) uint8_t  sV8[2][CCH][144];  // e4m3, 144B stride, conflict-free

    const int tid  = threadIdx.x;
    const int lane = tid & 31;
    const int g    = lane >> 2;
    const int c    = lane & 3;
    const int b    = blockIdx.y;
    const int m0   = blockIdx.x * TM + (tid >> 5) * 32;

    float kmax = g_kmax_part[b * 32];
    #pragma unroll
    for (int i = 1; i < 32; i++) kmax = fmaxf(kmax, g_kmax_part[b * 32 + i]);

    uint32_t qa0[2], qa1[2];
    float nsh[4];
    #pragma unroll
    for (int mt = 0; mt < 2; mt++) {
        const int rA = m0 + mt * 16 + g, rB = rA + 8;
        qa0[mt] = *(const uint32_t*)&g_q16[((size_t)b * NPIX + rA) * DQ + 2 * c];
        qa1[mt] = *(const uint32_t*)&g_q16[((size_t)b * NPIX + rB) * DQ + 2 * c];
        nsh[2*mt]   = -g_qn[b * NPIX + rA] * kmax * L2E;
        nsh[2*mt+1] = -g_qn[b * NPIX + rB] * kmax * L2E;
    }

    float acc[2][8][4];
    #pragma unroll
    for (int mt = 0; mt < 2; mt++)
        #pragma unroll
        for (int jc = 0; jc < 8; jc++)
            #pragma unroll
            for (int r = 0; r < 4; r++) acc[mt][jc][r] = 0.f;
    float ls[4] = {0.f, 0.f, 0.f, 0.f};

    const int src0 = (lane & 28) | ((c & 1) << 1);   // quad base + 0 or 2
    const int src1 = src0 + 1;
    const bool hij = (c >> 1);                        // j-half select

    STAGE(0, 0); CPCOMMIT();

    #pragma unroll 1
    for (int t = 0; t < NT; t++) {
        if (t + 1 < NT) { STAGE(t + 1, (t + 1) & 1); CPCOMMIT(); CPWAIT1(); }
        else            { CPWAIT0(); }
        __syncthreads();
        const __half (*K)[24] = sK[t & 1];
        const uint8_t (*V)[144] = sV8[t & 1];

        #pragma unroll
        for (int kc = 0; kc < 4; kc++) {           // 32-pixel chunks
            uint32_t R[2][4];                       // packed e4m3 P: [mt][j] = {g pair, g+8 pair}
            #pragma unroll
            for (int j = 0; j < 4; j++) {
                const uint32_t kb = *(const uint32_t*)&K[(kc * 4 + j) * 8 + g][2 * c];
                #pragma unroll
                for (int mt = 0; mt < 2; mt++) {
                    float s0, s1, s2, s3;
                    asm volatile(
                        "mma.sync.aligned.m16n8k8.row.col.f32.f16.f16.f32 "
                        "{%0,%1,%2,%3},{%4,%5},{%6},{%7,%8,%9,%10};"
                        : "=f"(s0), "=f"(s1), "=f"(s2), "=f"(s3)
                        : "r"(qa0[mt]), "r"(qa1[mt]), "r"(kb),
                          "f"(nsh[2*mt]), "f"(nsh[2*mt]), "f"(nsh[2*mt+1]), "f"(nsh[2*mt+1]));
                    uint32_t u0, u1, p0, p1;
                    asm("cvt.rn.f16x2.f32 %0, %1, %2;" : "=r"(u0) : "f"(s1), "f"(s0));
                    asm("cvt.rn.f16x2.f32 %0, %1, %2;" : "=r"(u1) : "f"(s3), "f"(s2));
                    asm("ex2.approx.f16x2 %0, %1;" : "=r"(p0) : "r"(u0));
                    asm("ex2.approx.f16x2 %0, %1;" : "=r"(p1) : "r"(u1));
                    // lsum on fma/alu pipes
                    {
                        __half2 hs = __hadd2(*(__half2*)&p0, __half2{__ushort_as_half(0), __ushort_as_half(0)});
                        float2 fA = __half22float2(*(__half2*)&p0);
                        float2 fB = __half22float2(*(__half2*)&p1);
                        (void)hs;
                        ls[2*mt]   += fA.x + fA.y;
                        ls[2*mt+1] += fB.x + fB.y;
                    }
                    uint16_t bg, bh;
                    asm("cvt.rn.satfinite.e4m3x2.f16x2 %0, %1;" : "=h"(bg) : "r"(p0));
                    asm("cvt.rn.satfinite.e4m3x2.f16x2 %0, %1;" : "=h"(bh) : "r"(p1));
                    R[mt][j] = (uint32_t)bg | ((uint32_t)bh << 16);
                }
            }
            // repack to m16n8k32 A-frags and do FP8 PV
            #pragma unroll
            for (int mt = 0; mt < 2; mt++) {
                uint32_t x0a = __shfl_sync(0xFFFFFFFFu, R[mt][0], src0);
                uint32_t x0b = __shfl_sync(0xFFFFFFFFu, R[mt][1], src0);
                uint32_t y0a = __shfl_sync(0xFFFFFFFFu, R[mt][0], src1);
                uint32_t y0b = __shfl_sync(0xFFFFFFFFu, R[mt][1], src1);
                uint32_t x1a = __shfl_sync(0xFFFFFFFFu, R[mt][2], src0);
                uint32_t x1b = __shfl_sync(0xFFFFFFFFu, R[mt][3], src0);
                uint32_t y1a = __shfl_sync(0xFFFFFFFFu, R[mt][2], src1);
                uint32_t y1b = __shfl_sync(0xFFFFFFFFu, R[mt][3], src1);
                uint32_t X0 = hij ? x0b : x0a;
                uint32_t Y0 = hij ? y0b : y0a;
                uint32_t X1 = hij ? x1b : x1a;
                uint32_t Y1 = hij ? y1b : y1a;
                uint32_t a0, a1, a2, a3;
                asm("prmt.b32 %0, %1, %2, 0x5410;" : "=r"(a0) : "r"(X0), "r"(Y0));
                asm("prmt.b32 %0, %1, %2, 0x7632;" : "=r"(a1) : "r"(X0), "r"(Y0));
                asm("prmt.b32 %0, %1, %2, 0x5410;" : "=r"(a2) : "r"(X1), "r"(Y1));
                asm("prmt.b32 %0, %1, %2, 0x7632;" : "=r"(a3) : "r"(X1), "r"(Y1));
                #pragma unroll
                for (int jc = 0; jc < 8; jc++) {
                    const uint32_t b0 = *(const uint32_t*)&V[jc * 8 + g][kc * 32 + 4 * c];
                    const uint32_t b1 = *(const uint32_t*)&V[jc * 8 + g][kc * 32 + 4 * c + 16];
                    asm volatile(
                        "mma.sync.aligned.m16n8k32.row.col.f32.e4m3.e4m3.f32 "
                        "{%0,%1,%2,%3},{%4,%5,%6,%7},{%8,%9},{%0,%1,%2,%3};"
                        : "+f"(acc[mt][jc][0]), "+f"(acc[mt][jc][1]),
                          "+f"(acc[mt][jc][2]), "+f"(acc[mt][jc][3])
                        : "r"(a0), "r"(a1), "r"(a2), "r"(a3),
                          "r"(b0), "r"(b1));
                }
            }
        }
        __syncthreads();
    }

    // quad-reduce lsum
    #pragma unroll
    for (int i = 0; i < 4; i++) {
        ls[i] += __shfl_xor_sync(0xFFFFFFFFu, ls[i], 1);
        ls[i] += __shfl_xor_sync(0xFFFFFFFFu, ls[i], 2);
    }

    const float gm = gamma[0];
    const float* xb = x   + (size_t)b * CCH * NPIX;
    float*       ob = out + (size_t)b * CCH * NPIX;
    #pragma unroll
    for (int mt = 0; mt < 2; mt++) {
        const float iA = 1.f / ls[2*mt], iB = 1.f / ls[2*mt+1];
        const int rA = m0 + mt * 16 + g, rB = rA + 8;
        #pragma unroll
        for (int jc = 0; jc < 8; jc++) {
            const int ch0 = jc * 8 + 2 * c, ch1 = ch0 + 1;
            ob[(size_t)ch0 * NPIX + rA] = fmaf(gm, acc[mt][jc][0] * iA, xb[(size_t)ch0 * NPIX + rA]);
            ob[(size_t)ch1 * NPIX + rA] = fmaf(gm, acc[mt][jc][1] * iA, xb[(size_t)ch1 * NPIX + rA]);
            ob[(size_t)ch0 * NPIX + rB] = fmaf(gm, acc[mt][jc][2] * iB, xb[(size_t)ch0 * NPIX + rB]);
            ob[(size_t)ch1 * NPIX + rB] = fmaf(gm, acc[mt][jc][3] * iB, xb[(size_t)ch1 * NPIX + rB]);
        }
    }
}

// ---------------------------------------------------------------------------
extern "C" void kernel_launch(void* const* d_in, const int* in_sizes, int n_in,
                              void* d_out, int out_size)
{
    const float* x     = (const float*)d_in[0];
    const float* wq    = (const float*)d_in[1];
    const float* bq    = (const float*)d_in[2];
    const float* wk    = (const float*)d_in[3];
    const float* bk    = (const float*)d_in[4];
    const float* wv    = (const float*)d_in[5];
    const float* bv    = (const float*)d_in[6];
    const float* gamma = (const float*)d_in[7];
    float* out = (float*)d_out;

    dim3 g1(NPIX / 128, BATCH);
    qkv_kernel<<<g1, 128>>>(x, wq, bq, wk, bk, wv, bv);
    dim3 g2(NPIX / TM, BATCH);
    attn_kernel<<<g2, TM>>>(x, gamma, out);
}

// round 9
// speedup vs baseline: 1.1230x; 1.0937x over previous
#include <cuda_runtime.h>
#include <cuda_fp16.h>
#include <cstdint>

#define BATCH 8
#define CCH   64
#define DQ    8
#define NPIX  4096
#define TM    128
#define TN    128
#define NT    (NPIX / TN)
#define L2E   1.4426950408889634f

__device__ __half   g_q16[BATCH * NPIX * DQ];               // pre-scaled by log2(e)
__device__ __half   g_k16[BATCH * NPIX * DQ];
__device__ float    g_qn[BATCH * NPIX];
__device__ uint8_t  g_v8[(size_t)BATCH * CCH * NPIX];       // e4m3 [b][c][n_perm]
__device__ float    g_kmax_part[BATCH * 32];

__device__ __forceinline__ uint32_t s2u(const void* p) {
    uint32_t a;
    asm("{ .reg .u64 t; cvta.to.shared.u64 t, %1; cvt.u32.u64 %0, t; }" : "=r"(a) : "l"(p));
    return a;
}
#define CP16(dst, src) asm volatile("cp.async.cg.shared.global [%0], [%1], 16;" :: "r"(dst), "l"(src) : "memory")
#define CPCOMMIT()     asm volatile("cp.async.commit_group;" ::: "memory")
#define CPWAIT1()      asm volatile("cp.async.wait_group 1;" ::: "memory")
#define CPWAIT0()      asm volatile("cp.async.wait_group 0;" ::: "memory")

// ---------------------------------------------------------------------------
// QKV projection (128 thr, grid (32, B)). q,k f16; v e4m3 stored with the
// FP8-A-fragment pixel permutation applied within each 32-pixel block.
// ---------------------------------------------------------------------------
__global__ __launch_bounds__(128) void qkv_kernel(
    const float* __restrict__ x,
    const float* __restrict__ wq, const float* __restrict__ bq,
    const float* __restrict__ wk, const float* __restrict__ bk,
    const float* __restrict__ wv, const float* __restrict__ bv)
{
    __shared__ float swq[DQ * CCH], swk[DQ * CCH], swv[CCH * CCH];
    __shared__ float sbq[DQ], sbk[DQ], sbv[CCH];
    __shared__ float swmax[4];

    const int tid = threadIdx.x;
    const int b = blockIdx.y;

    for (int i = tid; i < DQ * CCH; i += 128) { swq[i] = wq[i]; swk[i] = wk[i]; }
    for (int i = tid; i < CCH * CCH; i += 128) swv[i] = wv[i];
    if (tid < DQ) { sbq[tid] = bq[tid]; sbk[tid] = bk[tid]; }
    if (tid < CCH) sbv[tid] = bv[tid];
    __syncthreads();

    const int n = blockIdx.x * 128 + tid;

    float xv[CCH];
    const float* xb = x + ((size_t)b * CCH) * NPIX + n;
    #pragma unroll
    for (int c = 0; c < CCH; c++) xv[c] = xb[(size_t)c * NPIX];

    float qv[DQ], kv[DQ];
    #pragma unroll
    for (int d = 0; d < DQ; d++) {
        float aq = sbq[d], ak = sbk[d];
        #pragma unroll
        for (int c = 0; c < CCH; c++) {
            aq = fmaf(swq[d * CCH + c], xv[c], aq);
            ak = fmaf(swk[d * CCH + c], xv[c], ak);
        }
        qv[d] = aq; kv[d] = ak;
    }
    {
        __half2* qo = (__half2*)&g_q16[((size_t)b * NPIX + n) * DQ];
        __half2* ko = (__half2*)&g_k16[((size_t)b * NPIX + n) * DQ];
        #pragma unroll
        for (int d = 0; d < 4; d++) {
            qo[d] = __floats2half2_rn(qv[2*d] * L2E, qv[2*d+1] * L2E);
            ko[d] = __floats2half2_rn(kv[2*d], kv[2*d+1]);
        }
    }
    {
        float nq2 = 0.f, nk2 = 0.f;
        #pragma unroll
        for (int d = 0; d < DQ; d++) {
            nq2 = fmaf(qv[d], qv[d], nq2);
            nk2 = fmaf(kv[d], kv[d], nk2);
        }
        g_qn[b * NPIX + n] = sqrtf(nq2);
        float nk = sqrtf(nk2);
        #pragma unroll
        for (int off = 16; off > 0; off >>= 1)
            nk = fmaxf(nk, __shfl_xor_sync(0xFFFFFFFFu, nk, off));
        if ((tid & 31) == 0) swmax[tid >> 5] = nk;
        __syncthreads();
        if (tid == 0)
            g_kmax_part[b * 32 + blockIdx.x] =
                fmaxf(fmaxf(swmax[0], swmax[1]), fmaxf(swmax[2], swmax[3]));
    }
    // permuted pixel index for FP8 A-frag layout:
    // p = j*8 + 2*cp + e  ->  s = (j>>1)*16 + 4*cp + (j&1)*2 + e
    int n_perm;
    {
        int p = n & 31;
        int j = p >> 3, cp = (p & 7) >> 1, e = p & 1;
        int s = ((j >> 1) << 4) + (cp << 2) + ((j & 1) << 1) + e;
        n_perm = (n & ~31) | s;
    }
    #pragma unroll 4
    for (int o = 0; o < CCH; o += 2) {
        float a0 = sbv[o+0], a1 = sbv[o+1];
        #pragma unroll
        for (int c = 0; c < CCH; c++) {
            float xc = xv[c];
            a0 = fmaf(swv[(o+0)*CCH + c], xc, a0);
            a1 = fmaf(swv[(o+1)*CCH + c], xc, a1);
        }
        uint16_t pk;   // {hi = a1, lo = a0}
        asm("cvt.rn.satfinite.e4m3x2.f32 %0, %1, %2;" : "=h"(pk) : "f"(a1), "f"(a0));
        g_v8[((size_t)(b*CCH + o+0))*NPIX + n_perm] = (uint8_t)(pk & 0xFF);
        g_v8[((size_t)(b*CCH + o+1))*NPIX + n_perm] = (uint8_t)(pk >> 8);
    }
}

// ---------------------------------------------------------------------------
// Flash attention: S = f16 HMMA k8, P -> e4m3 local prmt pack (no shfl),
// PV = FP8 HMMA m16n8k32 on permuted-V. Grid (32, 8), 128 thr (4 warps).
// ---------------------------------------------------------------------------
#define STAGE(t, buf) do { \
    const __half* _ks = g_k16 + ((size_t)b * NPIX + (t) * TN + tid) * DQ; \
    CP16(s2u(&sK[buf][tid][0]), _ks); \
    _Pragma("unroll") \
    for (int _i = 0; _i < 4; _i++) { \
        int _l = _i * 128 + tid, _row = _l >> 3, _seg = _l & 7; \
        const uint8_t* _vs = g_v8 + ((size_t)(b * CCH + _row)) * NPIX + (t) * TN + _seg * 16; \
        CP16(s2u(&sV8[buf][_row][_seg * 16]), _vs); \
    } \
} while (0)

__global__ __launch_bounds__(128) void attn_kernel(
    const float* __restrict__ x,
    const float* __restrict__ gamma,
    float* __restrict__ out)
{
    __shared__ __align__(16) __half   sK[2][TN][24];     // 48B stride, conflict-free
    __shared__ __align__(16) uint8_t  sV8[2][CCH][144];  // e4m3 (permuted n), conflict-free

    const int tid  = threadIdx.x;
    const int lane = tid & 31;
    const int g    = lane >> 2;
    const int c    = lane & 3;
    const int b    = blockIdx.y;
    const int m0   = blockIdx.x * TM + (tid >> 5) * 32;

    float kmax = g_kmax_part[b * 32];
    #pragma unroll
    for (int i = 1; i < 32; i++) kmax = fmaxf(kmax, g_kmax_part[b * 32 + i]);

    uint32_t qa0[2], qa1[2];
    float nsh[4];
    #pragma unroll
    for (int mt = 0; mt < 2; mt++) {
        const int rA = m0 + mt * 16 + g, rB = rA + 8;
        qa0[mt] = *(const uint32_t*)&g_q16[((size_t)b * NPIX + rA) * DQ + 2 * c];
        qa1[mt] = *(const uint32_t*)&g_q16[((size_t)b * NPIX + rB) * DQ + 2 * c];
        nsh[2*mt]   = -g_qn[b * NPIX + rA] * kmax * L2E;
        nsh[2*mt+1] = -g_qn[b * NPIX + rB] * kmax * L2E;
    }

    float acc[2][8][4];
    #pragma unroll
    for (int mt = 0; mt < 2; mt++)
        #pragma unroll
        for (int jc = 0; jc < 8; jc++)
            #pragma unroll
            for (int r = 0; r < 4; r++) acc[mt][jc][r] = 0.f;
    float ls[4] = {0.f, 0.f, 0.f, 0.f};

    STAGE(0, 0); CPCOMMIT();

    #pragma unroll 1
    for (int t = 0; t < NT; t++) {
        if (t + 1 < NT) { STAGE(t + 1, (t + 1) & 1); CPCOMMIT(); CPWAIT1(); }
        else            { CPWAIT0(); }
        __syncthreads();
        const __half (*K)[24] = sK[t & 1];
        const uint8_t (*V)[144] = sV8[t & 1];

        #pragma unroll
        for (int kc = 0; kc < 4; kc++) {            // 32-pixel chunks
            uint32_t R[2][4];                        // [mt][j]: bytes {g:n2c, g:n2c+1, g8:n2c, g8:n2c+1}
            #pragma unroll
            for (int j = 0; j < 4; j++) {
                const uint32_t kb = *(const uint32_t*)&K[(kc * 4 + j) * 8 + g][2 * c];
                #pragma unroll
                for (int mt = 0; mt < 2; mt++) {
                    float s0, s1, s2, s3;
                    asm volatile(
                        "mma.sync.aligned.m16n8k8.row.col.f32.f16.f16.f32 "
                        "{%0,%1,%2,%3},{%4,%5},{%6},{%7,%8,%9,%10};"
                        : "=f"(s0), "=f"(s1), "=f"(s2), "=f"(s3)
                        : "r"(qa0[mt]), "r"(qa1[mt]), "r"(kb),
                          "f"(nsh[2*mt]), "f"(nsh[2*mt]), "f"(nsh[2*mt+1]), "f"(nsh[2*mt+1]));
                    uint32_t u0, u1, p0, p1;
                    asm("cvt.rn.f16x2.f32 %0, %1, %2;" : "=r"(u0) : "f"(s1), "f"(s0));
                    asm("cvt.rn.f16x2.f32 %0, %1, %2;" : "=r"(u1) : "f"(s3), "f"(s2));
                    asm("ex2.approx.f16x2 %0, %1;" : "=r"(p0) : "r"(u0));
                    asm("ex2.approx.f16x2 %0, %1;" : "=r"(p1) : "r"(u1));
                    float2 fA = __half22float2(*(__half2*)&p0);
                    float2 fB = __half22float2(*(__half2*)&p1);
                    ls[2*mt]   += fA.x + fA.y;
                    ls[2*mt+1] += fB.x + fB.y;
                    uint16_t bg, bh;
                    asm("cvt.rn.satfinite.e4m3x2.f16x2 %0, %1;" : "=h"(bg) : "r"(p0));
                    asm("cvt.rn.satfinite.e4m3x2.f16x2 %0, %1;" : "=h"(bh) : "r"(p1));
                    R[mt][j] = (uint32_t)bg | ((uint32_t)bh << 16);
                }
            }
            // local prmt pack -> A-frags (permuted V makes these k-slots line up)
            #pragma unroll
            for (int mt = 0; mt < 2; mt++) {
                uint32_t a0, a1, a2, a3;
                asm("prmt.b32 %0, %1, %2, 0x5410;" : "=r"(a0) : "r"(R[mt][0]), "r"(R[mt][1]));
                asm("prmt.b32 %0, %1, %2, 0x7632;" : "=r"(a1) : "r"(R[mt][0]), "r"(R[mt][1]));
                asm("prmt.b32 %0, %1, %2, 0x5410;" : "=r"(a2) : "r"(R[mt][2]), "r"(R[mt][3]));
                asm("prmt.b32 %0, %1, %2, 0x7632;" : "=r"(a3) : "r"(R[mt][2]), "r"(R[mt][3]));
                #pragma unroll
                for (int jc = 0; jc < 8; jc++) {
                    const uint32_t b0 = *(const uint32_t*)&V[jc * 8 + g][kc * 32 + 4 * c];
                    const uint32_t b1 = *(const uint32_t*)&V[jc * 8 + g][kc * 32 + 4 * c + 16];
                    asm volatile(
                        "mma.sync.aligned.m16n8k32.row.col.f32.e4m3.e4m3.f32 "
                        "{%0,%1,%2,%3},{%4,%5,%6,%7},{%8,%9},{%0,%1,%2,%3};"
                        : "+f"(acc[mt][jc][0]), "+f"(acc[mt][jc][1]),
                          "+f"(acc[mt][jc][2]), "+f"(acc[mt][jc][3])
                        : "r"(a0), "r"(a1), "r"(a2), "r"(a3),
                          "r"(b0), "r"(b1));
                }
            }
        }
        __syncthreads();
    }

    // quad-reduce lsum
    #pragma unroll
    for (int i = 0; i < 4; i++) {
        ls[i] += __shfl_xor_sync(0xFFFFFFFFu, ls[i], 1);
        ls[i] += __shfl_xor_sync(0xFFFFFFFFu, ls[i], 2);
    }

    const float gm = gamma[0];
    const float* xb = x   + (size_t)b * CCH * NPIX;
    float*       ob = out + (size_t)b * CCH * NPIX;
    #pragma unroll
    for (int mt = 0; mt < 2; mt++) {
        const float iA = 1.f / ls[2*mt], iB = 1.f / ls[2*mt+1];
        const int rA = m0 + mt * 16 + g, rB = rA + 8;
        #pragma unroll
        for (int jc = 0; jc < 8; jc++) {
            const int ch0 = jc * 8 + 2 * c, ch1 = ch0 + 1;
            ob[(size_t)ch0 * NPIX + rA] = fmaf(gm, acc[mt][jc][0] * iA, xb[(size_t)ch0 * NPIX + rA]);
            ob[(size_t)ch1 * NPIX + rA] = fmaf(gm, acc[mt][jc][1] * iA, xb[(size_t)ch1 * NPIX + rA]);
            ob[(size_t)ch0 * NPIX + rB] = fmaf(gm, acc[mt][jc][2] * iB, xb[(size_t)ch0 * NPIX + rB]);
            ob[(size_t)ch1 * NPIX + rB] = fmaf(gm, acc[mt][jc][3] * iB, xb[(size_t)ch1 * NPIX + rB]);
        }
    }
}

// ---------------------------------------------------------------------------
extern "C" void kernel_launch(void* const* d_in, const int* in_sizes, int n_in,
                              void* d_out, int out_size)
{
    const float* x     = (const float*)d_in[0];
    const float* wq    = (const float*)d_in[1];
    const float* bq    = (const float*)d_in[2];
    const float* wk    = (const float*)d_in[3];
    const float* bk    = (const float*)d_in[4];
    const float* wv    = (const float*)d_in[5];
    const float* bv    = (const float*)d_in[6];
    const float* gamma = (const float*)d_in[7];
    float* out = (float*)d_out;

    dim3 g1(NPIX / 128, BATCH);
    qkv_kernel<<<g1, 128>>>(x, wq, bq, wk, bk, wv, bv);
    dim3 g2(NPIX / TM, BATCH);
    attn_kernel<<<g2, TM>>>(x, gamma, out);
}

// round 10
// speedup vs baseline: 1.1652x; 1.0376x over previous
#include <cuda_runtime.h>
#include <cuda_fp16.h>
#include <cstdint>

#define BATCH 8
#define CCH   64
#define DQ    8
#define NPIX  4096
#define TM    128
#define TN    128
#define NT    (NPIX / TN)
#define L2E   1.4426950408889634f

__device__ __half   g_q16[BATCH * NPIX * DQ];               // pre-scaled by log2(e)
__device__ __half   g_k16[BATCH * NPIX * DQ];
__device__ float    g_qn[BATCH * NPIX];
__device__ uint8_t  g_v8[(size_t)BATCH * CCH * NPIX];       // e4m3 [b][c][n_perm]
__device__ float    g_kmax_part[BATCH * 32];

__device__ __forceinline__ uint32_t s2u(const void* p) {
    uint32_t a;
    asm("{ .reg .u64 t; cvta.to.shared.u64 t, %1; cvt.u32.u64 %0, t; }" : "=r"(a) : "l"(p));
    return a;
}
#define CP16(dst, src) asm volatile("cp.async.cg.shared.global [%0], [%1], 16;" :: "r"(dst), "l"(src) : "memory")
#define CPCOMMIT()     asm volatile("cp.async.commit_group;" ::: "memory")
#define CPWAIT1()      asm volatile("cp.async.wait_group 1;" ::: "memory")
#define CPWAIT0()      asm volatile("cp.async.wait_group 0;" ::: "memory")

// ---------------------------------------------------------------------------
// QKV projection (128 thr, grid (32, B)). q,k f16; v e4m3 stored with the
// FP8-A-fragment pixel permutation applied within each 32-pixel block.
// ---------------------------------------------------------------------------
__global__ __launch_bounds__(128) void qkv_kernel(
    const float* __restrict__ x,
    const float* __restrict__ wq, const float* __restrict__ bq,
    const float* __restrict__ wk, const float* __restrict__ bk,
    const float* __restrict__ wv, const float* __restrict__ bv)
{
    __shared__ float swq[DQ * CCH], swk[DQ * CCH], swv[CCH * CCH];
    __shared__ float sbq[DQ], sbk[DQ], sbv[CCH];
    __shared__ float swmax[4];

    const int tid = threadIdx.x;
    const int b = blockIdx.y;

    for (int i = tid; i < DQ * CCH; i += 128) { swq[i] = wq[i]; swk[i] = wk[i]; }
    for (int i = tid; i < CCH * CCH; i += 128) swv[i] = wv[i];
    if (tid < DQ) { sbq[tid] = bq[tid]; sbk[tid] = bk[tid]; }
    if (tid < CCH) sbv[tid] = bv[tid];
    __syncthreads();

    const int n = blockIdx.x * 128 + tid;

    float xv[CCH];
    const float* xb = x + ((size_t)b * CCH) * NPIX + n;
    #pragma unroll
    for (int c = 0; c < CCH; c++) xv[c] = xb[(size_t)c * NPIX];

    float qv[DQ], kv[DQ];
    #pragma unroll
    for (int d = 0; d < DQ; d++) {
        float aq = sbq[d], ak = sbk[d];
        #pragma unroll
        for (int c = 0; c < CCH; c++) {
            aq = fmaf(swq[d * CCH + c], xv[c], aq);
            ak = fmaf(swk[d * CCH + c], xv[c], ak);
        }
        qv[d] = aq; kv[d] = ak;
    }
    {
        __half2* qo = (__half2*)&g_q16[((size_t)b * NPIX + n) * DQ];
        __half2* ko = (__half2*)&g_k16[((size_t)b * NPIX + n) * DQ];
        #pragma unroll
        for (int d = 0; d < 4; d++) {
            qo[d] = __floats2half2_rn(qv[2*d] * L2E, qv[2*d+1] * L2E);
            ko[d] = __floats2half2_rn(kv[2*d], kv[2*d+1]);
        }
    }
    {
        float nq2 = 0.f, nk2 = 0.f;
        #pragma unroll
        for (int d = 0; d < DQ; d++) {
            nq2 = fmaf(qv[d], qv[d], nq2);
            nk2 = fmaf(kv[d], kv[d], nk2);
        }
        g_qn[b * NPIX + n] = sqrtf(nq2);
        float nk = sqrtf(nk2);
        #pragma unroll
        for (int off = 16; off > 0; off >>= 1)
            nk = fmaxf(nk, __shfl_xor_sync(0xFFFFFFFFu, nk, off));
        if ((tid & 31) == 0) swmax[tid >> 5] = nk;
        __syncthreads();
        if (tid == 0)
            g_kmax_part[b * 32 + blockIdx.x] =
                fmaxf(fmaxf(swmax[0], swmax[1]), fmaxf(swmax[2], swmax[3]));
    }
    // permuted pixel index for FP8 A-frag layout:
    // p = j*8 + 2*cp + e  ->  s = (j>>1)*16 + 4*cp + (j&1)*2 + e
    int n_perm;
    {
        int p = n & 31;
        int j = p >> 3, cp = (p & 7) >> 1, e = p & 1;
        int s = ((j >> 1) << 4) + (cp << 2) + ((j & 1) << 1) + e;
        n_perm = (n & ~31) | s;
    }
    #pragma unroll 4
    for (int o = 0; o < CCH; o += 2) {
        float a0 = sbv[o+0], a1 = sbv[o+1];
        #pragma unroll
        for (int c = 0; c < CCH; c++) {
            float xc = xv[c];
            a0 = fmaf(swv[(o+0)*CCH + c], xc, a0);
            a1 = fmaf(swv[(o+1)*CCH + c], xc, a1);
        }
        uint16_t pk;   // {hi = a1, lo = a0}
        asm("cvt.rn.satfinite.e4m3x2.f32 %0, %1, %2;" : "=h"(pk) : "f"(a1), "f"(a0));
        g_v8[((size_t)(b*CCH + o+0))*NPIX + n_perm] = (uint8_t)(pk & 0xFF);
        g_v8[((size_t)(b*CCH + o+1))*NPIX + n_perm] = (uint8_t)(pk >> 8);
    }
}

// ---------------------------------------------------------------------------
// Flash attention: S = f16 HMMA k8, P -> e4m3 prmt pack, PV + lsum = FP8
// HMMA m16n8k32 (V frags via ldmatrix.x4). Grid (32, 8), 128 thr (4 warps).
// ---------------------------------------------------------------------------
#define VSTRIDE 144
#define STAGE(t, buf) do { \
    const __half* _ks = g_k16 + ((size_t)b * NPIX + (t) * TN + tid) * DQ; \
    CP16(s2u(&sK[buf][tid][0]), _ks); \
    _Pragma("unroll") \
    for (int _i = 0; _i < 4; _i++) { \
        int _l = _i * 128 + tid, _row = _l >> 3, _seg = _l & 7; \
        const uint8_t* _vs = g_v8 + ((size_t)(b * CCH + _row)) * NPIX + (t) * TN + _seg * 16; \
        CP16(s2u(&sV8[buf][_row][_seg * 16]), _vs); \
    } \
} while (0)

__global__ __launch_bounds__(128) void attn_kernel(
    const float* __restrict__ x,
    const float* __restrict__ gamma,
    float* __restrict__ out)
{
    __shared__ __align__(16) __half   sK[2][TN][24];         // 48B stride, conflict-free
    __shared__ __align__(16) uint8_t  sV8[2][CCH][VSTRIDE];  // e4m3 (permuted n)

    const int tid  = threadIdx.x;
    const int lane = tid & 31;
    const int g    = lane >> 2;
    const int c    = lane & 3;
    const int b    = blockIdx.y;
    const int m0   = blockIdx.x * TM + (tid >> 5) * 32;

    float kmax = g_kmax_part[b * 32];
    #pragma unroll
    for (int i = 1; i < 32; i++) kmax = fmaxf(kmax, g_kmax_part[b * 32 + i]);

    uint32_t qa0[2], qa1[2];
    float nsh[4];
    #pragma unroll
    for (int mt = 0; mt < 2; mt++) {
        const int rA = m0 + mt * 16 + g, rB = rA + 8;
        qa0[mt] = *(const uint32_t*)&g_q16[((size_t)b * NPIX + rA) * DQ + 2 * c];
        qa1[mt] = *(const uint32_t*)&g_q16[((size_t)b * NPIX + rB) * DQ + 2 * c];
        nsh[2*mt]   = -g_qn[b * NPIX + rA] * kmax * L2E;
        nsh[2*mt+1] = -g_qn[b * NPIX + rB] * kmax * L2E;
    }

    // acc[mt][0..7] = channel tiles, acc[mt][8] = ones tile (lsum)
    float acc[2][9][4];
    #pragma unroll
    for (int mt = 0; mt < 2; mt++)
        #pragma unroll
        for (int jc = 0; jc < 9; jc++)
            #pragma unroll
            for (int r = 0; r < 4; r++) acc[mt][jc][r] = 0.f;

    // ldmatrix per-lane base address (jp=0, kc=0, buf=0):
    // lane l = 8*i + r : matrix i -> row (i>>1)*8 + r, byte col (i&1)*16
    const uint32_t vb0 = s2u(&sV8[0][(lane >> 4) * 8 + (lane & 7)][((lane >> 3) & 1) * 16]);

    STAGE(0, 0); CPCOMMIT();

    #pragma unroll 1
    for (int t = 0; t < NT; t++) {
        if (t + 1 < NT) { STAGE(t + 1, (t + 1) & 1); CPCOMMIT(); CPWAIT1(); }
        else            { CPWAIT0(); }
        __syncthreads();
        const __half (*K)[24] = sK[t & 1];
        const uint32_t vbase = vb0 + (uint32_t)((t & 1) * CCH * VSTRIDE);

        #pragma unroll
        for (int kc = 0; kc < 4; kc++) {            // 32-pixel chunks
            uint32_t R[2][4];                        // packed e4m3 P
            #pragma unroll
            for (int j = 0; j < 4; j++) {
                const uint32_t kb = *(const uint32_t*)&K[(kc * 4 + j) * 8 + g][2 * c];
                #pragma unroll
                for (int mt = 0; mt < 2; mt++) {
                    float s0, s1, s2, s3;
                    asm volatile(
                        "mma.sync.aligned.m16n8k8.row.col.f32.f16.f16.f32 "
                        "{%0,%1,%2,%3},{%4,%5},{%6},{%7,%8,%9,%10};"
                        : "=f"(s0), "=f"(s1), "=f"(s2), "=f"(s3)
                        : "r"(qa0[mt]), "r"(qa1[mt]), "r"(kb),
                          "f"(nsh[2*mt]), "f"(nsh[2*mt]), "f"(nsh[2*mt+1]), "f"(nsh[2*mt+1]));
                    uint32_t u0, u1, p0, p1;
                    asm("cvt.rn.f16x2.f32 %0, %1, %2;" : "=r"(u0) : "f"(s1), "f"(s0));
                    asm("cvt.rn.f16x2.f32 %0, %1, %2;" : "=r"(u1) : "f"(s3), "f"(s2));
                    asm("ex2.approx.f16x2 %0, %1;" : "=r"(p0) : "r"(u0));
                    asm("ex2.approx.f16x2 %0, %1;" : "=r"(p1) : "r"(u1));
                    uint16_t bg, bh;
                    asm("cvt.rn.satfinite.e4m3x2.f16x2 %0, %1;" : "=h"(bg) : "r"(p0));
                    asm("cvt.rn.satfinite.e4m3x2.f16x2 %0, %1;" : "=h"(bh) : "r"(p1));
                    R[mt][j] = (uint32_t)bg | ((uint32_t)bh << 16);
                }
            }
            // local prmt pack -> A-frags (permuted V lines up the k-slots)
            uint32_t af[2][4];
            #pragma unroll
            for (int mt = 0; mt < 2; mt++) {
                asm("prmt.b32 %0, %1, %2, 0x5410;" : "=r"(af[mt][0]) : "r"(R[mt][0]), "r"(R[mt][1]));
                asm("prmt.b32 %0, %1, %2, 0x7632;" : "=r"(af[mt][1]) : "r"(R[mt][0]), "r"(R[mt][1]));
                asm("prmt.b32 %0, %1, %2, 0x5410;" : "=r"(af[mt][2]) : "r"(R[mt][2]), "r"(R[mt][3]));
                asm("prmt.b32 %0, %1, %2, 0x7632;" : "=r"(af[mt][3]) : "r"(R[mt][2]), "r"(R[mt][3]));
            }
            // PV: V frags via ldmatrix.x4 (jc-pair per load)
            #pragma unroll
            for (int jp = 0; jp < 4; jp++) {
                uint32_t b00, b01, b10, b11;   // b0/b1 of jc=2jp, b0/b1 of jc=2jp+1
                const uint32_t va = vbase + (uint32_t)(jp * 16 * VSTRIDE + kc * 32);
                asm volatile("ldmatrix.sync.aligned.m8n8.x4.shared.b16 {%0,%1,%2,%3}, [%4];"
                    : "=r"(b00), "=r"(b01), "=r"(b10), "=r"(b11) : "r"(va));
                #pragma unroll
                for (int mt = 0; mt < 2; mt++) {
                    asm volatile(
                        "mma.sync.aligned.m16n8k32.row.col.f32.e4m3.e4m3.f32 "
                        "{%0,%1,%2,%3},{%4,%5,%6,%7},{%8,%9},{%0,%1,%2,%3};"
                        : "+f"(acc[mt][2*jp][0]), "+f"(acc[mt][2*jp][1]),
                          "+f"(acc[mt][2*jp][2]), "+f"(acc[mt][2*jp][3])
                        : "r"(af[mt][0]), "r"(af[mt][1]), "r"(af[mt][2]), "r"(af[mt][3]),
                          "r"(b00), "r"(b01));
                    asm volatile(
                        "mma.sync.aligned.m16n8k32.row.col.f32.e4m3.e4m3.f32 "
                        "{%0,%1,%2,%3},{%4,%5,%6,%7},{%8,%9},{%0,%1,%2,%3};"
                        : "+f"(acc[mt][2*jp+1][0]), "+f"(acc[mt][2*jp+1][1]),
                          "+f"(acc[mt][2*jp+1][2]), "+f"(acc[mt][2*jp+1][3])
                        : "r"(af[mt][0]), "r"(af[mt][1]), "r"(af[mt][2]), "r"(af[mt][3]),
                          "r"(b10), "r"(b11));
                }
            }
            // lsum: ones-MMA on the tensor pipe (e4m3 1.0 = 0x38)
            #pragma unroll
            for (int mt = 0; mt < 2; mt++) {
                const uint32_t ones = 0x38383838u;
                asm volatile(
                    "mma.sync.aligned.m16n8k32.row.col.f32.e4m3.e4m3.f32 "
                    "{%0,%1,%2,%3},{%4,%5,%6,%7},{%8,%9},{%0,%1,%2,%3};"
                    : "+f"(acc[mt][8][0]), "+f"(acc[mt][8][1]),
                      "+f"(acc[mt][8][2]), "+f"(acc[mt][8][3])
                    : "r"(af[mt][0]), "r"(af[mt][1]), "r"(af[mt][2]), "r"(af[mt][3]),
                      "r"(ones), "r"(ones));
            }
        }
        __syncthreads();
    }

    // lsum: every lane's ones-tile cols are identical; no reduce needed.
    const float gm = gamma[0];
    const float* xb = x   + (size_t)b * CCH * NPIX;
    float*       ob = out + (size_t)b * CCH * NPIX;
    #pragma unroll
    for (int mt = 0; mt < 2; mt++) {
        const float iA = 1.f / acc[mt][8][0];
        const float iB = 1.f / acc[mt][8][2];
        const int rA = m0 + mt * 16 + g, rB = rA + 8;
        #pragma unroll
        for (int jc = 0; jc < 8; jc++) {
            const int ch0 = jc * 8 + 2 * c, ch1 = ch0 + 1;
            ob[(size_t)ch0 * NPIX + rA] = fmaf(gm, acc[mt][jc][0] * iA, xb[(size_t)ch0 * NPIX + rA]);
            ob[(size_t)ch1 * NPIX + rA] = fmaf(gm, acc[mt][jc][1] * iA, xb[(size_t)ch1 * NPIX + rA]);
            ob[(size_t)ch0 * NPIX + rB] = fmaf(gm, acc[mt][jc][2] * iB, xb[(size_t)ch0 * NPIX + rB]);
            ob[(size_t)ch1 * NPIX + rB] = fmaf(gm, acc[mt][jc][3] * iB, xb[(size_t)ch1 * NPIX + rB]);
        }
    }
}

// ---------------------------------------------------------------------------
extern "C" void kernel_launch(void* const* d_in, const int* in_sizes, int n_in,
                              void* d_out, int out_size)
{
    const float* x     = (const float*)d_in[0];
    const float* wq    = (const float*)d_in[1];
    const float* bq    = (const float*)d_in[2];
    const float* wk    = (const float*)d_in[3];
    const float* bk    = (const float*)d_in[4];
    const float* wv    = (const float*)d_in[5];
    const float* bv    = (const float*)d_in[6];
    const float* gamma = (const float*)d_in[7];
    float* out = (float*)d_out;

    dim3 g1(NPIX / 128, BATCH);
    qkv_kernel<<<g1, 128>>>(x, wq, bq, wk, bk, wv, bv);
    dim3 g2(NPIX / TM, BATCH);
    attn_kernel<<<g2, TM>>>(x, gamma, out);
}